// round 17
// baseline (speedup 1.0000x reference)
#include <cuda_runtime.h>

#define IMG_H 512
#define IMG_W 512

typedef unsigned long long u64;

__constant__ u64   c_k2[9];    // conv weights packed {k,k}
__constant__ float c_pw[22];   // [0]=a/2, [1]=b/2, [2..11]=g_j, [12..21]=d_j/2
__constant__ int   c_cnt;      // interior-unit count (even, 0..10)

__device__ u64   d_k2s[9];
__device__ float d_pws[22];
__device__ int   d_cnts;

__device__ __forceinline__ u64 pack2(float lo, float hi) {
    u64 r; asm("mov.b64 %0, {%1, %2};" : "=l"(r) : "f"(lo), "f"(hi)); return r;
}
__device__ __forceinline__ void unpack2(u64 v, float& lo, float& hi) {
    asm("mov.b64 {%0, %1}, %2;" : "=f"(lo), "=f"(hi) : "l"(v));
}
__device__ __forceinline__ u64 ffma2(u64 a, u64 b, u64 c) {
    u64 r; asm("fma.rn.f32x2 %0, %1, %2, %3;" : "=l"(r) : "l"(a), "l"(b), "l"(c)); return r;
}
__device__ __forceinline__ u64 fmul2(u64 a, u64 b) {
    u64 r; asm("mul.rn.f32x2 %0, %1, %2;" : "=l"(r) : "l"(a), "l"(b)); return r;
}
__device__ __forceinline__ u64 fadd2(u64 a, u64 b) {
    u64 r; asm("add.rn.f32x2 %0, %1, %2;" : "=l"(r) : "l"(a), "l"(b)); return r;
}

// s(g)/2 = a2*g + b2 + sum_j d2_j*|g - g_j|; act = 0.5*tanh(s/2) == sigmoid(s)-0.5
__global__ void prep_kernel(const float* __restrict__ k,
                            const float* __restrict__ w1,
                            const float* __restrict__ b1,
                            const float* __restrict__ w2) {
    if (threadIdx.x != 0 || blockIdx.x != 0) return;
    for (int i = 0; i < 9; ++i) d_k2s[i] = pack2(k[i], k[i]);
    float a = 0.0f, b = 0.0f;
    int cnt = 0;
    float gj[10], dj[10];
    for (int j = 0; j < 10; ++j) {
        float W1 = w1[j], B1 = b1[j], W2 = w2[j];
        a += 0.5f * W2 * W1;
        b += 0.5f * W2 * B1;
        bool always_on  = (B1 >= 0.0f) && (W1 + B1 >= 0.0f);
        bool always_off = (B1 <= 0.0f) && (W1 + B1 <= 0.0f);
        if (always_on)       { a += 0.5f * W2 * W1; b += 0.5f * W2 * B1; }
        else if (always_off) { a -= 0.5f * W2 * W1; b -= 0.5f * W2 * B1; }
        else { gj[cnt] = -B1 / W1; dj[cnt] = 0.5f * W2 * fabsf(W1); cnt++; }
    }
    if (cnt & 1) { gj[cnt] = 0.0f; dj[cnt] = 0.0f; cnt++; }
    d_pws[0] = 0.5f * a;
    d_pws[1] = 0.5f * b;
    for (int j = 0; j < 10; ++j) {
        d_pws[2 + j]  = (j < cnt) ? gj[j] : 0.0f;
        d_pws[12 + j] = (j < cnt) ? (0.5f * dj[j]) : 0.0f;
    }
    d_cnts = cnt;
}

#define L2E 1.4426950408889634f

// returns tanh(s/2); caller applies x + 0.5*th
template <int N>
__device__ __forceinline__ float act_th(float v) {
    float q = fmaf(v, -L2E, 2.0f * L2E);
    q = fmaf(q, v, -L2E);                                     // -L2E*(v-1)^2
    float g; asm("ex2.approx.f32 %0, %1;" : "=f"(g) : "f"(q));
    float h0 = fmaf(c_pw[0], g, c_pw[1]);
    float h1 = 0.0f;                                          // split accumulators
#pragma unroll
    for (int j = 0; j < N; j += 2) {
        h0 = fmaf(c_pw[12 + j],     fabsf(g - c_pw[2 + j]),     h0);
        h1 = fmaf(c_pw[12 + j + 1], fabsf(g - c_pw[2 + j + 1]), h1);
    }
    float hh = h0 + h1;
    float th; asm("tanh.approx.f32 %0, %1;" : "=f"(th) : "f"(hh));
    return th;
}

// two-tree packed conv on a 3x3 window of pair-registers
__device__ __forceinline__ u64 conv_pair(const u64* rm, const u64* rc, const u64* rp) {
    u64 vA = fmul2(c_k2[0], rm[0]);
    vA = ffma2(c_k2[1], rm[1], vA);
    vA = ffma2(c_k2[2], rm[2], vA);
    vA = ffma2(c_k2[3], rc[0], vA);
    u64 vB = fmul2(c_k2[4], rc[1]);
    vB = ffma2(c_k2[5], rc[2], vB);
    vB = ffma2(c_k2[6], rp[0], vB);
    vB = ffma2(c_k2[7], rp[1], vB);
    vB = ffma2(c_k2[8], rp[2], vB);
    return fadd2(vA, vB);
}

// Geometry: output tile 64 cols x 32 rows. Smem coord: gc = cb+(c-4), gy = y0+(r-2).
// S0: input rows 0..35, cols 2..69. S1: step-1 result rows 1..34, cols 2..69.
#define TILE_W  64
#define TILE_H  32
#define SSTRIDE 72
#define SROWS   36

// flat one-pair step update (used only for 132 edge units of pass 1)
template <int N>
__device__ __forceinline__ void nca_flat(const float* __restrict__ S, int r, int c,
                                         float& o0, float& o1) {
    const float* p0 = S + (r - 1) * SSTRIDE + c;
    const float* p1 = S + (r    ) * SSTRIDE + c;
    const float* p2 = S + (r + 1) * SSTRIDE + c;
    float2 m0 = *reinterpret_cast<const float2*>(p0);
    float2 m1 = *reinterpret_cast<const float2*>(p1);
    float2 m2 = *reinterpret_cast<const float2*>(p2);
    u64 A[3] = { pack2(p0[-1], m0.x), pack2(m0.x, m0.y), pack2(m0.y, p0[2]) };
    u64 B[3] = { pack2(p1[-1], m1.x), pack2(m1.x, m1.y), pack2(m1.y, p1[2]) };
    u64 C[3] = { pack2(p2[-1], m2.x), pack2(m2.x, m2.y), pack2(m2.y, p2[2]) };
    u64 v = conv_pair(A, B, C);
    float f0, f1;
    unpack2(v, f0, f1);
    o0 = fmaf(0.5f, act_th<N>(f0), m1.x);
    o1 = fmaf(0.5f, act_th<N>(f1), m1.y);
}

template <int N, bool TWO>
__device__ __forceinline__ void fused_tile(const float* __restrict__ img,
                                           float* __restrict__ out1,
                                           float* __restrict__ out2,
                                           float* __restrict__ S0,
                                           float* __restrict__ S1,
                                           int cb, int y0) {
    const int tx  = threadIdx.x;
    const int ty  = threadIdx.y;
    const int tid = ty * 32 + tx;

    // ---- stage input tile (+2 halo) into S0 ----
    for (int i = tid; i < SROWS * (TILE_W / 4); i += 256) {
        int r = i >> 4, q = i & 15;
        int gy = y0 + r - 2;
        float4 v = make_float4(0.f, 0.f, 0.f, 0.f);
        if ((unsigned)gy < IMG_H)
            v = *reinterpret_cast<const float4*>(img + gy * IMG_W + cb + q * 4);
        *reinterpret_cast<float4*>(S0 + r * SSTRIDE + 4 + q * 4) = v;
    }
    for (int i = tid; i < SROWS * 2; i += 256) {
        int r = i >> 1, side = i & 1;
        int gy = y0 + r - 2;
        int gc = side ? (cb + TILE_W) : (cb - 2);
        float2 v = make_float2(0.f, 0.f);
        if ((unsigned)gy < IMG_H && (unsigned)gc < IMG_W)
            v = *reinterpret_cast<const float2*>(img + gy * IMG_W + gc);
        *reinterpret_cast<float2*>(S0 + r * SSTRIDE + (side ? (4 + TILE_W) : 2)) = v;
    }
    __syncthreads();

    const int colb = 4 + 2 * tx;            // smem col of this thread's pair
    const int gc   = cb + 2 * tx;           // global col of pair (interior pairs)

    // ---- pass 1 (window): step s+1 at rows r=1+4ty .. 4+4ty, pair cols 4..66 ----
    {
        const int rbase = 4 * ty;           // (first output row) - 1
        u64 win[3][3];
        float tl, t0, t1, tr;
        auto fetch = [&](int r) {
            const float* row = S0 + r * SSTRIDE;
            float2 v = *reinterpret_cast<const float2*>(row + colb);
            tl = row[colb - 1]; tr = row[colb + 2]; t0 = v.x; t1 = v.y;
        };
        auto commit = [&](u64* P) {
            P[0] = pack2(tl, t0); P[1] = pack2(t0, t1); P[2] = pack2(t1, tr);
        };
        fetch(rbase);     commit(win[0]);
        fetch(rbase + 1); commit(win[1]);
        fetch(rbase + 2);
#pragma unroll
        for (int t = 0; t < 4; ++t) {
            const int r = 1 + 4 * ty + t;
            u64* rm = win[(t + 0) % 3];
            u64* rc = win[(t + 1) % 3];
            u64* rp = win[(t + 2) % 3];
            commit(rp);
            if (t < 3) fetch(rbase + t + 3);

            u64 v = conv_pair(rm, rc, rp);
            float f0, f1, x0, x1;
            unpack2(v, f0, f1);
            unpack2(rc[1], x0, x1);
            float o0 = fmaf(0.5f, act_th<N>(f0), x0);
            float o1 = fmaf(0.5f, act_th<N>(f1), x1);

            // zero out-of-image values (SAME padding for pass 2's conv)
            int gy = y0 + r - 2;
            float r0 = ((unsigned)gy < IMG_H && (unsigned)gc       < IMG_W) ? o0 : 0.0f;
            float r1 = ((unsigned)gy < IMG_H && (unsigned)(gc + 1) < IMG_W) ? o1 : 0.0f;
            *reinterpret_cast<float2*>(S1 + r * SSTRIDE + colb) = make_float2(r0, r1);
            if (r >= 2)   // interior rows 2..32 here; row 33 handled in flat part
                *reinterpret_cast<float2*>(out1 + gy * IMG_W + gc) = make_float2(r0, r1);
        }
    }

    // ---- pass 1 (flat edges): rows 33,34 all pairs; rows 1..32 pairs {0,33} ----
    for (int i = tid; i < 132; i += 256) {
        int r, p;
        if (i < 68) { r = 33 + (i >= 34); p = (i < 34) ? i : (i - 34); }
        else        { int idx = i - 68; r = 1 + (idx >> 1); p = (idx & 1) ? 33 : 0; }
        int c = 2 + 2 * p;
        float o0, o1;
        nca_flat<N>(S0, r, c, o0, o1);
        int gy = y0 + r - 2;
        int gcf = cb + c - 4;
        float r0 = ((unsigned)gy < IMG_H && (unsigned)gcf       < IMG_W) ? o0 : 0.0f;
        float r1 = ((unsigned)gy < IMG_H && (unsigned)(gcf + 1) < IMG_W) ? o1 : 0.0f;
        *reinterpret_cast<float2*>(S1 + r * SSTRIDE + c) = make_float2(r0, r1);
        if (r >= 2 && r <= 33 && p >= 1 && p <= 32)        // only r=33 interior pairs
            *reinterpret_cast<float2*>(out1 + gy * IMG_W + gcf) = make_float2(r0, r1);
    }

    if (!TWO) return;
    __syncthreads();

    // ---- pass 2 (window): step s+2 at rows r=2+4ty .. 5+4ty, pair cols 4..66 ----
    {
        const int rbase = 1 + 4 * ty;
        u64 win[3][3];
        float tl, t0, t1, tr;
        auto fetch = [&](int r) {
            const float* row = S1 + r * SSTRIDE;
            float2 v = *reinterpret_cast<const float2*>(row + colb);
            tl = row[colb - 1]; tr = row[colb + 2]; t0 = v.x; t1 = v.y;
        };
        auto commit = [&](u64* P) {
            P[0] = pack2(tl, t0); P[1] = pack2(t0, t1); P[2] = pack2(t1, tr);
        };
        fetch(rbase);     commit(win[0]);
        fetch(rbase + 1); commit(win[1]);
        fetch(rbase + 2);
#pragma unroll
        for (int t = 0; t < 4; ++t) {
            const int r = 2 + 4 * ty + t;
            u64* rm = win[(t + 0) % 3];
            u64* rc = win[(t + 1) % 3];
            u64* rp = win[(t + 2) % 3];
            commit(rp);
            if (t < 3) fetch(rbase + t + 3);

            u64 v = conv_pair(rm, rc, rp);
            float f0, f1, x0, x1;
            unpack2(v, f0, f1);
            unpack2(rc[1], x0, x1);
            float2 o;
            o.x = fmaf(0.5f, act_th<N>(f0), x0);
            o.y = fmaf(0.5f, act_th<N>(f1), x1);
            *reinterpret_cast<float2*>(out2 + (y0 + r - 2) * IMG_W + gc) = o;
        }
    }
}

template <bool TWO>
__global__ __launch_bounds__(256, 7) void step_kernel(const float* __restrict__ in,
                                                      float* __restrict__ out1,
                                                      float* __restrict__ out2) {
    __shared__ float S0[SROWS * SSTRIDE];
    __shared__ float S1[SROWS * SSTRIDE];
    const int cb = blockIdx.x * TILE_W;
    const int y0 = blockIdx.y * TILE_H;
    const int b  = blockIdx.z;

    const float* img = in   + (size_t)b * (IMG_H * IMG_W);
    float* o1        = out1 + (size_t)b * (IMG_H * IMG_W);
    float* o2        = out2 + (size_t)b * (IMG_H * IMG_W);

    const int n = c_cnt;
    if      (n == 0)  fused_tile<0 , TWO>(img, o1, o2, S0, S1, cb, y0);
    else if (n == 2)  fused_tile<2 , TWO>(img, o1, o2, S0, S1, cb, y0);
    else if (n == 4)  fused_tile<4 , TWO>(img, o1, o2, S0, S1, cb, y0);
    else if (n == 6)  fused_tile<6 , TWO>(img, o1, o2, S0, S1, cb, y0);
    else if (n == 8)  fused_tile<8 , TWO>(img, o1, o2, S0, S1, cb, y0);
    else              fused_tile<10, TWO>(img, o1, o2, S0, S1, cb, y0);
}

extern "C" void kernel_launch(void* const* d_in, const int* in_sizes, int n_in,
                              void* d_out, int out_size) {
    const float* x  = (const float*)d_in[0];
    const float* k  = (const float*)d_in[1];
    const float* w1 = (const float*)d_in[2];
    const float* b1 = (const float*)d_in[3];
    const float* w2 = (const float*)d_in[4];
    float* out = (float*)d_out;

    const int npix  = in_sizes[0];
    const int B     = npix / (IMG_H * IMG_W);
    const int steps = out_size / npix - 1;

    prep_kernel<<<1, 32>>>(k, w1, b1, w2);
    void *pk2 = nullptr, *ppw = nullptr, *pcnt = nullptr;
    cudaGetSymbolAddress(&pk2,  d_k2s);
    cudaGetSymbolAddress(&ppw,  d_pws);
    cudaGetSymbolAddress(&pcnt, d_cnts);
    cudaMemcpyToSymbolAsync(c_k2,  pk2,  9 * sizeof(u64),    0, cudaMemcpyDeviceToDevice, 0);
    cudaMemcpyToSymbolAsync(c_pw,  ppw,  22 * sizeof(float), 0, cudaMemcpyDeviceToDevice, 0);
    cudaMemcpyToSymbolAsync(c_cnt, pcnt, sizeof(int),        0, cudaMemcpyDeviceToDevice, 0);

    cudaMemcpyAsync(out, x, (size_t)npix * sizeof(float), cudaMemcpyDeviceToDevice, 0);

    dim3 blk(32, 8, 1);
    dim3 grd(IMG_W / TILE_W, IMG_H / TILE_H, B);   // (8, 16, B)

    int s = 0;
    while (steps - s >= 2) {
        step_kernel<true><<<grd, blk>>>(out + (size_t)s * npix,
                                        out + (size_t)(s + 1) * npix,
                                        out + (size_t)(s + 2) * npix);
        s += 2;
    }
    if (s < steps) {
        step_kernel<false><<<grd, blk>>>(out + (size_t)s * npix,
                                         out + (size_t)(s + 1) * npix,
                                         out + (size_t)(s + 1) * npix);
    }
}